// round 1
// baseline (speedup 1.0000x reference)
#include <cuda_runtime.h>

#define LAMBDA_COORD 5.0f
#define LAMBDA_NO_OBJ 0.5f

__global__ void zero_out_kernel(float* out) {
    out[0] = 0.0f;
}

__device__ __forceinline__ float warp_reduce(float v) {
    #pragma unroll
    for (int off = 16; off > 0; off >>= 1)
        v += __shfl_xor_sync(0xFFFFFFFFu, v, off);
    return v;
}

__global__ void yolo_loss_kernel(
    const float*  __restrict__ main_boxes,   // [M,4]
    const float4* __restrict__ pred_boxes,   // [P] of float4
    const float*  __restrict__ conf,         // [P]
    const float4* __restrict__ gmp,          // [NP4]
    const float4* __restrict__ gpp,          // [NP4]
    const int*    __restrict__ matched_main, // [P]
    const float*  __restrict__ matched_iou,  // [P]
    float* __restrict__ out,
    int P, int NP4)
{
    const int tid    = blockIdx.x * blockDim.x + threadIdx.x;
    const int stride = gridDim.x * blockDim.x;

    float acc = 0.0f;

    // ---- prob loss: sum((gmp - gpp)^2), vectorized float4 ----
    for (int i = tid; i < NP4; i += stride) {
        float4 a = gmp[i];
        float4 b = gpp[i];
        float d0 = a.x - b.x;
        float d1 = a.y - b.y;
        float d2 = a.z - b.z;
        float d3 = a.w - b.w;
        acc = fmaf(d0, d0, acc);
        acc = fmaf(d1, d1, acc);
        acc = fmaf(d2, d2, acc);
        acc = fmaf(d3, d3, acc);
    }

    // ---- box loss ----
    for (int p = tid; p < P; p += stride) {
        int   mm = matched_main[p];
        float c  = conf[p];
        if (mm >= 0) {
            float4 pb = pred_boxes[p];
            // gather GT box (4 floats, coalesce poorly but only 1024 matched rows -> L2/L1 hits)
            const float* mbp = main_boxes + (size_t)mm * 4;
            float mx = mbp[0], my = mbp[1], mw = mbp[2], mh = mbp[3];

            float dx = mx - pb.x;
            float dy = my - pb.y;
            float xy = dx * dx + dy * dy;

            float sw = sqrtf(fmaxf(mw, 0.0f)) - sqrtf(fmaxf(pb.z, 0.0f));
            float sh = sqrtf(fmaxf(mh, 0.0f)) - sqrtf(fmaxf(pb.w, 0.0f));
            float wh = sw * sw + sh * sh;

            float di = matched_iou[p] - c;
            acc += LAMBDA_COORD * (xy + wh) + di * di;
        } else {
            acc += LAMBDA_NO_OBJ * c * c;
        }
    }

    // ---- block reduction ----
    __shared__ float warp_sums[32];
    float wsum = warp_reduce(acc);
    int lane = threadIdx.x & 31;
    int wid  = threadIdx.x >> 5;
    if (lane == 0) warp_sums[wid] = wsum;
    __syncthreads();

    int nwarps = blockDim.x >> 5;
    if (wid == 0) {
        float v = (lane < nwarps) ? warp_sums[lane] : 0.0f;
        v = warp_reduce(v);
        if (lane == 0) atomicAdd(out, v);
    }
}

extern "C" void kernel_launch(void* const* d_in, const int* in_sizes, int n_in,
                              void* d_out, int out_size) {
    const float*  main_boxes   = (const float*) d_in[0];
    const float4* pred_boxes   = (const float4*)d_in[1];
    const float*  conf         = (const float*) d_in[2];
    const float4* gmp          = (const float4*)d_in[3];
    const float4* gpp          = (const float4*)d_in[4];
    const int*    matched_main = (const int*)   d_in[5];
    const float*  matched_iou  = (const float*) d_in[6];
    float* out = (float*)d_out;

    int P   = in_sizes[2];      // 32768 (boxes_confidence element count)
    int NP4 = in_sizes[3] / 4;  // 1310720 / 4 = 327680

    zero_out_kernel<<<1, 1>>>(out);

    const int threads = 256;
    const int blocks  = 296;    // ~2 blocks/SM on 148 SMs
    yolo_loss_kernel<<<blocks, threads>>>(
        main_boxes, pred_boxes, conf, gmp, gpp, matched_main, matched_iou,
        out, P, NP4);
}